// round 2
// baseline (speedup 1.0000x reference)
#include <cuda_runtime.h>

#define K_IN 5
#define OCH 2
#define NN 4096
#define NE 131072
#define TOT (K_IN * NE)   // 655360 edges per matrix

// ---------------- scratch (device globals; no allocations) ----------------
__device__ float g_ws[2][OCH][K_IN];      // [0]=softmax(w1), [1]=softmax(w2)
__device__ int   g_cnt[NN];               // row histogram
__device__ int   g_off[NN + 1];           // CSR row offsets (shared by A1/A2)
__device__ int   g_cur[NN];               // scatter cursor
__device__ float g_a1val[OCH][TOT];       // A1 values per channel
__device__ int2  g_a2pair[OCH][TOT];      // {col, float_as_int(A2 val)} per channel

// ---------------- kernel 1: softmax weights + zero histogram ----------------
__global__ void k_init(const float* __restrict__ w1, const float* __restrict__ w2,
                       float* __restrict__ outw /* = d_out + H elems */) {
    int t = threadIdx.x;
    for (int i = t; i < NN; i += blockDim.x) g_cnt[i] = 0;
    if (t < 2 * OCH) {
        int which = t >> 1, o = t & 1;
        const float* w = which ? w2 : w1;
        float v[K_IN];
        float mx = -1e30f;
        #pragma unroll
        for (int k = 0; k < K_IN; k++) { v[k] = w[o * K_IN + k]; mx = fmaxf(mx, v[k]); }
        float s = 0.f;
        #pragma unroll
        for (int k = 0; k < K_IN; k++) { v[k] = expf(v[k] - mx); s += v[k]; }
        float inv = 1.f / s;
        #pragma unroll
        for (int k = 0; k < K_IN; k++) {
            float sv = v[k] * inv;
            g_ws[which][o][k] = sv;
            outw[which * (OCH * K_IN) + o * K_IN + k] = sv;  // W1 then W2
        }
    }
}

// ---------------- kernel 2: row histogram ----------------
__global__ void k_hist(const int* __restrict__ ei) {
    int i = blockIdx.x * blockDim.x + threadIdx.x;
    if (i >= TOT) return;
    int k = i / NE, e = i - k * NE;
    int row = ei[(size_t)k * 2 * NE + e];
    atomicAdd(&g_cnt[row], 1);
}

// ---------------- kernel 3: exclusive scan (4096 elems, 1 block) ----------------
__global__ void k_scan() {
    __shared__ int s[1024];
    int t = threadIdx.x;
    int c0 = g_cnt[4 * t + 0], c1 = g_cnt[4 * t + 1];
    int c2 = g_cnt[4 * t + 2], c3 = g_cnt[4 * t + 3];
    int sum = c0 + c1 + c2 + c3;
    s[t] = sum;
    __syncthreads();
    for (int d = 1; d < 1024; d <<= 1) {
        int v = (t >= d) ? s[t - d] : 0;
        __syncthreads();
        s[t] += v;
        __syncthreads();
    }
    int excl = s[t] - sum;                 // exclusive prefix for this thread's 4
    int o0 = excl, o1 = o0 + c0, o2 = o1 + c1, o3 = o2 + c2;
    g_off[4 * t + 0] = o0;  g_off[4 * t + 1] = o1;
    g_off[4 * t + 2] = o2;  g_off[4 * t + 3] = o3;
    g_cur[4 * t + 0] = o0;  g_cur[4 * t + 1] = o1;
    g_cur[4 * t + 2] = o2;  g_cur[4 * t + 3] = o3;
    if (t == 1023) g_off[NN] = s[1023];
}

// ---------------- kernel 4: scatter edges into CSR slots ----------------
__global__ void k_scatter(const int* __restrict__ ei,
                          const float* __restrict__ evals) {
    int i = blockIdx.x * blockDim.x + threadIdx.x;
    if (i >= TOT) return;
    int k = i / NE, e = i - k * NE;
    int row = ei[(size_t)k * 2 * NE + e];
    int col = ei[(size_t)k * 2 * NE + NE + e];
    float ev = evals[(size_t)k * NE + e];
    int slot = atomicAdd(&g_cur[row], 1);
    #pragma unroll
    for (int o = 0; o < OCH; o++) {
        g_a1val[o][slot] = g_ws[0][o][k] * ev;
        int2 p;
        p.x = col;
        p.y = __float_as_int(g_ws[1][o][k] * ev);
        g_a2pair[o][slot] = p;
    }
}

// ---------------- kernel 5: row-wise SpGEMM, dense 16KB smem accumulator ----------------
__global__ void __launch_bounds__(256) k_spgemm(float* __restrict__ H) {
    __shared__ float acc[NN];              // 16 KB
    int n = blockIdx.x;                    // output row
    int o = blockIdx.y;                    // channel
    for (int i = threadIdx.x; i < NN; i += 256) acc[i] = 0.f;
    __syncthreads();

    int rs = g_off[n], re = g_off[n + 1];
    int warp = threadIdx.x >> 5, lane = threadIdx.x & 31;
    const float* __restrict__ a1 = g_a1val[o];
    const int2*  __restrict__ a2 = g_a2pair[o];

    for (int j = rs + warp; j < re; j += 8) {
        int   m  = a2[j].x;                // column of A1 entry (shared pattern)
        float v1 = a1[j];
        int ms, me;
        if (lane == 0) { ms = g_off[m]; me = g_off[m + 1]; }
        ms = __shfl_sync(0xFFFFFFFFu, ms, 0);
        me = __shfl_sync(0xFFFFFFFFu, me, 0);
        for (int t = ms + lane; t < me; t += 32) {
            int2 p = a2[t];
            atomicAdd(&acc[p.x], v1 * __int_as_float(p.y));
        }
    }
    __syncthreads();

    float4* __restrict__ dst =
        (float4*)(H + ((size_t)o * NN + (size_t)n) * NN);
    const float4* src = (const float4*)acc;
    for (int i = threadIdx.x; i < NN / 4; i += 256) dst[i] = src[i];
}

// ---------------- launch ----------------
extern "C" void kernel_launch(void* const* d_in, const int* in_sizes, int n_in,
                              void* d_out, int out_size) {
    const int*   ei = (const int*)d_in[0];     // edge_index [5,2,E] int32 (JAX x64 off)
    const float* ev = (const float*)d_in[1];   // edge_value [5,E]
    const float* w1 = (const float*)d_in[2];   // [2,5]
    const float* w2 = (const float*)d_in[3];   // [2,5]
    float* out = (float*)d_out;
    const size_t H_ELEMS = (size_t)OCH * NN * NN;  // 33,554,432

    k_init<<<1, 256>>>(w1, w2, out + H_ELEMS);
    k_hist<<<(TOT + 255) / 256, 256>>>(ei);
    k_scan<<<1, 1024>>>();
    k_scatter<<<(TOT + 255) / 256, 256>>>(ei, ev);
    dim3 grid(NN, OCH);
    k_spgemm<<<grid, 256>>>(out);
}

// round 3
// speedup vs baseline: 1.0046x; 1.0046x over previous
#include <cuda_runtime.h>

#define K_IN 5
#define OCH 2
#define NN 4096
#define NE 131072
#define TOT (K_IN * NE)   // 655360 edges per matrix

// ---------------- scratch (device globals; no allocations) ----------------
__device__ float  g_ws[2][OCH][K_IN];   // [0]=softmax(w1), [1]=softmax(w2)
__device__ int    g_cnt[NN];            // row histogram
__device__ int    g_off[NN + 1];        // CSR row offsets (shared pattern)
__device__ int    g_cur[NN];            // scatter cursor
__device__ int    g_col[TOT];           // column index per entry (shared by A1/A2)
__device__ float2 g_a1[TOT];            // A1 values {ch0, ch1}
__device__ float2 g_a2[TOT];            // A2 values {ch0, ch1}

// ---------------- kernel 1: softmax weights + zero histogram ----------------
__global__ void k_init(const float* __restrict__ w1, const float* __restrict__ w2,
                       float* __restrict__ outw /* = d_out + H elems */) {
    int t = threadIdx.x;
    for (int i = t; i < NN; i += blockDim.x) g_cnt[i] = 0;
    if (t < 2 * OCH) {
        int which = t >> 1, o = t & 1;
        const float* w = which ? w2 : w1;
        float v[K_IN];
        float mx = -1e30f;
        #pragma unroll
        for (int k = 0; k < K_IN; k++) { v[k] = w[o * K_IN + k]; mx = fmaxf(mx, v[k]); }
        float s = 0.f;
        #pragma unroll
        for (int k = 0; k < K_IN; k++) { v[k] = expf(v[k] - mx); s += v[k]; }
        float inv = 1.f / s;
        #pragma unroll
        for (int k = 0; k < K_IN; k++) {
            float sv = v[k] * inv;
            g_ws[which][o][k] = sv;
            outw[which * (OCH * K_IN) + o * K_IN + k] = sv;  // W1 then W2
        }
    }
}

// ---------------- kernel 2: row histogram ----------------
__global__ void k_hist(const int* __restrict__ ei) {
    int i = blockIdx.x * blockDim.x + threadIdx.x;
    if (i >= TOT) return;
    int k = i / NE, e = i - k * NE;
    int row = ei[(size_t)k * 2 * NE + e];
    atomicAdd(&g_cnt[row], 1);
}

// ---------------- kernel 3: exclusive scan (4096 elems, 1 block) ----------------
__global__ void k_scan() {
    __shared__ int s[1024];
    int t = threadIdx.x;
    int c0 = g_cnt[4 * t + 0], c1 = g_cnt[4 * t + 1];
    int c2 = g_cnt[4 * t + 2], c3 = g_cnt[4 * t + 3];
    int sum = c0 + c1 + c2 + c3;
    s[t] = sum;
    __syncthreads();
    for (int d = 1; d < 1024; d <<= 1) {
        int v = (t >= d) ? s[t - d] : 0;
        __syncthreads();
        s[t] += v;
        __syncthreads();
    }
    int excl = s[t] - sum;
    int o0 = excl, o1 = o0 + c0, o2 = o1 + c1, o3 = o2 + c2;
    g_off[4 * t + 0] = o0;  g_off[4 * t + 1] = o1;
    g_off[4 * t + 2] = o2;  g_off[4 * t + 3] = o3;
    g_cur[4 * t + 0] = o0;  g_cur[4 * t + 1] = o1;
    g_cur[4 * t + 2] = o2;  g_cur[4 * t + 3] = o3;
    if (t == 1023) g_off[NN] = s[1023];
}

// ---------------- kernel 4: scatter edges into CSR slots (fused channels) ----------------
__global__ void k_scatter(const int* __restrict__ ei,
                          const float* __restrict__ evals) {
    int i = blockIdx.x * blockDim.x + threadIdx.x;
    if (i >= TOT) return;
    int k = i / NE, e = i - k * NE;
    int row = ei[(size_t)k * 2 * NE + e];
    int col = ei[(size_t)k * 2 * NE + NE + e];
    float ev = evals[(size_t)k * NE + e];
    int slot = atomicAdd(&g_cur[row], 1);
    g_col[slot] = col;
    g_a1[slot] = make_float2(g_ws[0][0][k] * ev, g_ws[0][1][k] * ev);
    g_a2[slot] = make_float2(g_ws[1][0][k] * ev, g_ws[1][1][k] * ev);
}

// ---------------- kernel 5: row-wise SpGEMM, both channels fused ----------------
// One block per output row n: traverses the shared sparsity pattern ONCE,
// accumulating both output channels into two planar 16KB smem arrays.
__global__ void __launch_bounds__(256) k_spgemm(float* __restrict__ H) {
    __shared__ float acc0[NN];             // channel 0 (planar: bank = col % 32)
    __shared__ float acc1[NN];             // channel 1
    int n = blockIdx.x;
    for (int i = threadIdx.x; i < NN; i += 256) { acc0[i] = 0.f; acc1[i] = 0.f; }
    __syncthreads();

    int rs = g_off[n], re = g_off[n + 1];
    int warp = threadIdx.x >> 5, lane = threadIdx.x & 31;

    for (int j = rs + warp; j < re; j += 8) {
        int    m  = g_col[j];              // A1 column == A2 row (shared pattern)
        float2 v1 = g_a1[j];               // A1 values, both channels
        int ms, me;
        if (lane == 0) { ms = g_off[m]; me = g_off[m + 1]; }
        ms = __shfl_sync(0xFFFFFFFFu, ms, 0);
        me = __shfl_sync(0xFFFFFFFFu, me, 0);
        for (int t = ms + lane; t < me; t += 32) {
            int    c  = g_col[t];
            float2 v2 = g_a2[t];
            atomicAdd(&acc0[c], v1.x * v2.x);
            atomicAdd(&acc1[c], v1.y * v2.y);
        }
    }
    __syncthreads();

    float4* __restrict__ d0 = (float4*)(H + (size_t)n * NN);
    float4* __restrict__ d1 = (float4*)(H + (size_t)NN * NN + (size_t)n * NN);
    const float4* s0 = (const float4*)acc0;
    const float4* s1 = (const float4*)acc1;
    for (int i = threadIdx.x; i < NN / 4; i += 256) { d0[i] = s0[i]; d1[i] = s1[i]; }
}

// ---------------- launch ----------------
extern "C" void kernel_launch(void* const* d_in, const int* in_sizes, int n_in,
                              void* d_out, int out_size) {
    const int*   ei = (const int*)d_in[0];     // edge_index [5,2,E] int32
    const float* ev = (const float*)d_in[1];   // edge_value [5,E]
    const float* w1 = (const float*)d_in[2];   // [2,5]
    const float* w2 = (const float*)d_in[3];   // [2,5]
    float* out = (float*)d_out;
    const size_t H_ELEMS = (size_t)OCH * NN * NN;  // 33,554,432

    k_init<<<1, 256>>>(w1, w2, out + H_ELEMS);
    k_hist<<<(TOT + 255) / 256, 256>>>(ei);
    k_scan<<<1, 1024>>>();
    k_scatter<<<(TOT + 255) / 256, 256>>>(ei, ev);
    k_spgemm<<<NN, 256>>>(out);
}